// round 15
// baseline (speedup 1.0000x reference)
#include <cuda_runtime.h>
#include <cuda_bf16.h>
#include <math.h>

#define Bz 32
#define Dd 768
#define D3 2304
#define Xx 256
#define VV 30522
#define VP 30720          // 240*128 padded vocab
#define NB 240            // k3 v-blocks of 128
#define BW 960
#define Jj 4
#define Kk 8
#define NCH 24            // k3 k-chunks of 32
#define NCHH 6            // k1h k-chunks per z-quarter
#define GSZ (D3 * Bz)
// smem element offsets (bf16 elems), rows padded to 40 (80B, conflict-free)
#define SA_H 0
#define SA_L 5120
#define SH_H 10240
#define SH_L 11520
#define SBUF 12800        // elems per buffer (25600 B)

// ---------------- persistent device scratch ----------------
__device__ float g_h[Bz * Dd];
__device__ float g_x[Bz * Dd];
__device__ float g_ctx[Bz * Dd];
__device__ float g_giT[4 * GSZ];
__device__ float g_ghT[4 * GSZ];
__device__ float g_attn[Bz * Xx];
__device__ float g_attn_n[Bz * Xx];
__device__ float g_pgen[Bz];
__device__ float g_inv[Bz];
__device__ __align__(16) float g_e[Bz * VP];
__device__ float g_psum[Bz * NB];
__device__ unsigned long long g_pkey[Bz * NB];
__device__ unsigned int g_bit[Bz * BW];
__device__ __align__(16) __nv_bfloat16 g_ebh[(size_t)VP * Dd];
__device__ __align__(16) __nv_bfloat16 g_ebl[(size_t)VP * Dd];
__device__ __align__(16) __nv_bfloat16 g_wih_h[(size_t)D3 * Dd];
__device__ __align__(16) __nv_bfloat16 g_wih_l[(size_t)D3 * Dd];
__device__ __align__(16) __nv_bfloat16 g_whh_h[(size_t)D3 * Dd];
__device__ __align__(16) __nv_bfloat16 g_whh_l[(size_t)D3 * Dd];
__device__ __align__(16) __nv_bfloat16 g_hhb[Bz * Dd];
__device__ __align__(16) __nv_bfloat16 g_hlb[Bz * Dd];
__device__ __align__(16) __nv_bfloat16 g_xhb[Bz * Dd];
__device__ __align__(16) __nv_bfloat16 g_xlb[Bz * Dd];

__device__ __forceinline__ float sigf(float x) { return 1.0f / (1.0f + expf(-x)); }

__device__ __forceinline__ unsigned int s2u(const void* p) {
    unsigned int a;
    asm("{ .reg .u64 t; cvta.to.shared.u64 t, %1; cvt.u32.u64 %0, t; }" : "=r"(a) : "l"(p));
    return a;
}
__device__ __forceinline__ void cpa16(unsigned int d, const void* s) {
    asm volatile("cp.async.cg.shared.global [%0], [%1], 16;" :: "r"(d), "l"(s) : "memory");
}
__device__ __forceinline__ void mma_bf16(float* d, unsigned a0, unsigned a1,
                                         unsigned a2, unsigned a3,
                                         unsigned b0, unsigned b1) {
    asm volatile(
        "mma.sync.aligned.m16n8k16.row.col.f32.bf16.bf16.f32 "
        "{%0,%1,%2,%3}, {%4,%5,%6,%7}, {%8,%9}, {%0,%1,%2,%3};"
        : "+f"(d[0]), "+f"(d[1]), "+f"(d[2]), "+f"(d[3])
        : "r"(a0), "r"(a1), "r"(a2), "r"(a3), "r"(b0), "r"(b1));
}

// ================= shared GEMM bodies =================

// k1h body: gate GEMM quarter. which: 0=ih(x), 1=hh(h).
__device__ void k1h_body(__nv_bfloat16* sm, int vtile, int z,
                         const float* __restrict__ bias, int which) {
    int t = threadIdx.x, w = t >> 5, lane = t & 31;
    int q = lane & 3, r8 = lane >> 2;
    int vbase = vtile << 7;
    int ko0 = z * (NCHH * 32);
    unsigned int sbase = s2u(sm);

    const __nv_bfloat16 *Wh, *Wl, *Bh, *Bl;
    float* OT;
    if (which == 0) {
        Wh = g_wih_h; Wl = g_wih_l; Bh = g_xhb; Bl = g_xlb;
        OT = g_giT + z * GSZ;
    } else {
        Wh = g_whh_h; Wl = g_whh_l; Bh = g_hhb; Bl = g_hlb;
        OT = g_ghT + z * GSZ;
    }

    float acc[4][4];
    #pragma unroll
    for (int nt = 0; nt < 4; nt++)
        #pragma unroll
        for (int i = 0; i < 4; i++) acc[nt][i] = 0.f;

    int lr = t >> 2, lc = (t & 3) * 8;
    int hr = (t & 127) >> 2, hc = ((t & 127) & 3) * 8;
    const __nv_bfloat16* gA0h = Wh + (size_t)(vbase + lr) * Dd + lc + ko0;
    const __nv_bfloat16* gA1h = Wh + (size_t)(vbase + lr + 64) * Dd + lc + ko0;
    const __nv_bfloat16* gA0l = Wl + (size_t)(vbase + lr) * Dd + lc + ko0;
    const __nv_bfloat16* gA1l = Wl + (size_t)(vbase + lr + 64) * Dd + lc + ko0;
    const __nv_bfloat16* gH = (t < 128 ? Bh : Bl) + (size_t)hr * Dd + hc + ko0;
    unsigned int dA0 = (unsigned)((SA_H + lr * 40 + lc) * 2);
    unsigned int dA1 = (unsigned)((SA_H + (lr + 64) * 40 + lc) * 2);
    unsigned int dL0 = (unsigned)((SA_L + lr * 40 + lc) * 2);
    unsigned int dL1 = (unsigned)((SA_L + (lr + 64) * 40 + lc) * 2);
    unsigned int dH = (unsigned)(((t < 128 ? SH_H : SH_L) + hr * 40 + hc) * 2);

    cpa16(sbase + dA0, gA0h);
    cpa16(sbase + dA1, gA1h);
    cpa16(sbase + dL0, gA0l);
    cpa16(sbase + dL1, gA1l);
    cpa16(sbase + dH, gH);
    asm volatile("cp.async.commit_group;" ::: "memory");
    asm volatile("cp.async.wait_group 0;" ::: "memory");
    __syncthreads();

    for (int kc = 0; kc < NCHH; kc++) {
        int buf = kc & 1;
        if (kc + 1 < NCHH) {
            unsigned int nb = sbase + (buf ^ 1) * (SBUF * 2);
            int ko = (kc + 1) * 32;
            cpa16(nb + dA0, gA0h + ko);
            cpa16(nb + dA1, gA1h + ko);
            cpa16(nb + dL0, gA0l + ko);
            cpa16(nb + dL1, gA1l + ko);
            cpa16(nb + dH, gH + ko);
            asm volatile("cp.async.commit_group;" ::: "memory");
        }
        const __nv_bfloat16* Ah = sm + buf * SBUF + SA_H;
        const __nv_bfloat16* Al = sm + buf * SBUF + SA_L;
        const __nv_bfloat16* Hh = sm + buf * SBUF + SH_H;
        const __nv_bfloat16* Hl = sm + buf * SBUF + SH_L;
        int ar = w * 16 + r8;
        #pragma unroll
        for (int s = 0; s < 2; s++) {
            int k0 = s * 16, ac = k0 + q * 2;
            unsigned ah0 = *(const unsigned*)&Ah[ar * 40 + ac];
            unsigned ah1 = *(const unsigned*)&Ah[(ar + 8) * 40 + ac];
            unsigned ah2 = *(const unsigned*)&Ah[ar * 40 + ac + 8];
            unsigned ah3 = *(const unsigned*)&Ah[(ar + 8) * 40 + ac + 8];
            unsigned al0 = *(const unsigned*)&Al[ar * 40 + ac];
            unsigned al1 = *(const unsigned*)&Al[(ar + 8) * 40 + ac];
            unsigned al2 = *(const unsigned*)&Al[ar * 40 + ac + 8];
            unsigned al3 = *(const unsigned*)&Al[(ar + 8) * 40 + ac + 8];
            #pragma unroll
            for (int nt = 0; nt < 4; nt++) {
                int bn = (nt * 8 + r8) * 40 + k0 + q * 2;
                unsigned bh0 = *(const unsigned*)&Hh[bn];
                unsigned bh1 = *(const unsigned*)&Hh[bn + 8];
                unsigned bl0 = *(const unsigned*)&Hl[bn];
                unsigned bl1 = *(const unsigned*)&Hl[bn + 8];
                mma_bf16(acc[nt], ah0, ah1, ah2, ah3, bh0, bh1);
                mma_bf16(acc[nt], al0, al1, al2, al3, bh0, bh1);
                mma_bf16(acc[nt], ah0, ah1, ah2, ah3, bl0, bl1);
            }
        }
        if (kc + 1 < NCHH)
            asm volatile("cp.async.wait_group 0;" ::: "memory");
        __syncthreads();
    }

    int v0 = vbase + w * 16 + r8, v1 = v0 + 8;
    float bi0 = z ? 0.f : bias[v0];
    float bi1 = z ? 0.f : bias[v1];
    #pragma unroll
    for (int nt = 0; nt < 4; nt++) {
        int b0 = nt * 8 + q * 2, b1 = b0 + 1;
        OT[(size_t)v0 * 32 + b0] = acc[nt][0] + bi0;
        OT[(size_t)v0 * 32 + b1] = acc[nt][1] + bi0;
        OT[(size_t)v1 * 32 + b0] = acc[nt][2] + bi1;
        OT[(size_t)v1 * 32 + b1] = acc[nt][3] + bi1;
    }
}

// k3 body: e = exp(emb @ h^T), fused partial sums + argmax keys.
__device__ void k3_body(__nv_bfloat16* sm, int blk) {
    __shared__ float sSum[8][32];
    __shared__ unsigned long long sKey[8][32];
    int t = threadIdx.x, w = t >> 5, lane = t & 31;
    int q = lane & 3, r8 = lane >> 2;
    int vbase = blk << 7;
    unsigned int sbase = s2u(sm);

    float acc[4][4];
    #pragma unroll
    for (int nt = 0; nt < 4; nt++)
        #pragma unroll
        for (int i = 0; i < 4; i++) acc[nt][i] = 0.f;

    int lr = t >> 2, lc = (t & 3) * 8;
    int hr = (t & 127) >> 2, hc = ((t & 127) & 3) * 8;
    const __nv_bfloat16* gA0h = g_ebh + (size_t)(vbase + lr) * Dd + lc;
    const __nv_bfloat16* gA1h = g_ebh + (size_t)(vbase + lr + 64) * Dd + lc;
    const __nv_bfloat16* gA0l = g_ebl + (size_t)(vbase + lr) * Dd + lc;
    const __nv_bfloat16* gA1l = g_ebl + (size_t)(vbase + lr + 64) * Dd + lc;
    const __nv_bfloat16* gH = (t < 128 ? g_hhb : g_hlb) + (size_t)hr * Dd + hc;
    unsigned int dA0 = (unsigned)((SA_H + lr * 40 + lc) * 2);
    unsigned int dA1 = (unsigned)((SA_H + (lr + 64) * 40 + lc) * 2);
    unsigned int dL0 = (unsigned)((SA_L + lr * 40 + lc) * 2);
    unsigned int dL1 = (unsigned)((SA_L + (lr + 64) * 40 + lc) * 2);
    unsigned int dH = (unsigned)(((t < 128 ? SH_H : SH_L) + hr * 40 + hc) * 2);

    cpa16(sbase + dA0, gA0h);
    cpa16(sbase + dA1, gA1h);
    cpa16(sbase + dL0, gA0l);
    cpa16(sbase + dL1, gA1l);
    cpa16(sbase + dH, gH);
    asm volatile("cp.async.commit_group;" ::: "memory");
    asm volatile("cp.async.wait_group 0;" ::: "memory");
    __syncthreads();

    for (int kc = 0; kc < NCH; kc++) {
        int buf = kc & 1;
        if (kc + 1 < NCH) {
            unsigned int nb = sbase + (buf ^ 1) * (SBUF * 2);
            int ko = (kc + 1) * 32;
            cpa16(nb + dA0, gA0h + ko);
            cpa16(nb + dA1, gA1h + ko);
            cpa16(nb + dL0, gA0l + ko);
            cpa16(nb + dL1, gA1l + ko);
            cpa16(nb + dH, gH + ko);
            asm volatile("cp.async.commit_group;" ::: "memory");
        }
        const __nv_bfloat16* Ah = sm + buf * SBUF + SA_H;
        const __nv_bfloat16* Al = sm + buf * SBUF + SA_L;
        const __nv_bfloat16* Hh = sm + buf * SBUF + SH_H;
        const __nv_bfloat16* Hl = sm + buf * SBUF + SH_L;
        int ar = w * 16 + r8;
        #pragma unroll
        for (int s = 0; s < 2; s++) {
            int k0 = s * 16, ac = k0 + q * 2;
            unsigned ah0 = *(const unsigned*)&Ah[ar * 40 + ac];
            unsigned ah1 = *(const unsigned*)&Ah[(ar + 8) * 40 + ac];
            unsigned ah2 = *(const unsigned*)&Ah[ar * 40 + ac + 8];
            unsigned ah3 = *(const unsigned*)&Ah[(ar + 8) * 40 + ac + 8];
            unsigned al0 = *(const unsigned*)&Al[ar * 40 + ac];
            unsigned al1 = *(const unsigned*)&Al[(ar + 8) * 40 + ac];
            unsigned al2 = *(const unsigned*)&Al[ar * 40 + ac + 8];
            unsigned al3 = *(const unsigned*)&Al[(ar + 8) * 40 + ac + 8];
            #pragma unroll
            for (int nt = 0; nt < 4; nt++) {
                int bn = (nt * 8 + r8) * 40 + k0 + q * 2;
                unsigned bh0 = *(const unsigned*)&Hh[bn];
                unsigned bh1 = *(const unsigned*)&Hh[bn + 8];
                unsigned bl0 = *(const unsigned*)&Hl[bn];
                unsigned bl1 = *(const unsigned*)&Hl[bn + 8];
                mma_bf16(acc[nt], ah0, ah1, ah2, ah3, bh0, bh1);
                mma_bf16(acc[nt], al0, al1, al2, al3, bh0, bh1);
                mma_bf16(acc[nt], ah0, ah1, ah2, ah3, bl0, bl1);
            }
        }
        if (kc + 1 < NCH)
            asm volatile("cp.async.wait_group 0;" ::: "memory");
        __syncthreads();
    }

    int v0 = vbase + w * 16 + r8, v1 = v0 + 8;
    bool ok0 = v0 < VV, ok1 = v1 < VV;
    #pragma unroll
    for (int nt = 0; nt < 4; nt++) {
        float e00 = ok0 ? __expf(acc[nt][0]) : 0.f;
        float e01 = ok0 ? __expf(acc[nt][1]) : 0.f;
        float e10 = ok1 ? __expf(acc[nt][2]) : 0.f;
        float e11 = ok1 ? __expf(acc[nt][3]) : 0.f;
        int b0 = nt * 8 + q * 2, b1 = b0 + 1;
        g_e[(size_t)b0 * VP + v0] = e00;
        g_e[(size_t)b1 * VP + v0] = e01;
        g_e[(size_t)b0 * VP + v1] = e10;
        g_e[(size_t)b1 * VP + v1] = e11;
        float s0 = e00 + e10, s1 = e01 + e11;
        unsigned long long k00 = ((unsigned long long)__float_as_uint(e00) << 32) | (unsigned)(~v0);
        unsigned long long k10 = ((unsigned long long)__float_as_uint(e10) << 32) | (unsigned)(~v1);
        unsigned long long k01 = ((unsigned long long)__float_as_uint(e01) << 32) | (unsigned)(~v0);
        unsigned long long k11 = ((unsigned long long)__float_as_uint(e11) << 32) | (unsigned)(~v1);
        unsigned long long key0 = k00 > k10 ? k00 : k10;
        unsigned long long key1 = k01 > k11 ? k01 : k11;
        #pragma unroll
        for (int o = 4; o <= 16; o <<= 1) {
            s0 += __shfl_xor_sync(0xffffffffu, s0, o);
            s1 += __shfl_xor_sync(0xffffffffu, s1, o);
            unsigned long long t0 = __shfl_xor_sync(0xffffffffu, key0, o);
            unsigned long long t1 = __shfl_xor_sync(0xffffffffu, key1, o);
            if (t0 > key0) key0 = t0;
            if (t1 > key1) key1 = t1;
        }
        if (r8 == 0) {
            sSum[w][b0] = s0; sSum[w][b1] = s1;
            sKey[w][b0] = key0; sKey[w][b1] = key1;
        }
    }
    __syncthreads();
    if (t < 32) {
        float s = 0.f;
        unsigned long long k = 0ull;
        #pragma unroll
        for (int w2 = 0; w2 < 8; w2++) {
            s += sSum[w2][t];
            if (sKey[w2][t] > k) k = sKey[w2][t];
        }
        g_psum[t * NB + blk] = s;
        g_pkey[t * NB + blk] = k;
    }
}

// k2b body: attention scores for (b, xc); hs = 768-float smem scratch.
__device__ void k2b_body(float* hs, int b, int xc,
                         const float* __restrict__ enc, const int* __restrict__ ids) {
    int t = threadIdx.x, lane = t & 31, w = t >> 5;
    for (int d = t; d < Dd; d += 256) hs[d] = g_h[(size_t)b * Dd + d];
    __syncthreads();
    #pragma unroll
    for (int i = 0; i < 4; i++) {
        int xi = xc * 32 + w * 4 + i;
        const float* er = enc + ((size_t)b * Xx + xi) * Dd;
        float s = 0.f;
        #pragma unroll
        for (int kk = 0; kk < 6; kk++) {
            float4 e4 = *(const float4*)(er + kk * 128 + lane * 4);
            float4 h4 = *(const float4*)(hs + kk * 128 + lane * 4);
            s += e4.x * h4.x + e4.y * h4.y + e4.z * h4.z + e4.w * h4.w;
        }
        #pragma unroll
        for (int o = 16; o; o >>= 1) s += __shfl_xor_sync(0xffffffffu, s, o);
        if (lane == 0)
            g_attn[b * Xx + xi] = (ids[b * Xx + xi] == 0) ? -1e9f : s;
    }
}

// ================= kernels =================

__global__ void init_kernel(const float* __restrict__ hidden) {
    int i = blockIdx.x * 256 + threadIdx.x;
    if (i < Bz * Dd) {
        float x = hidden[i];
        g_h[i] = x;
        __nv_bfloat16 hi = __float2bfloat16(x);
        g_hhb[i] = hi;
        g_hlb[i] = __float2bfloat16(x - __bfloat162float(hi));
    }
}
__global__ void bit_kernel(const int* __restrict__ ids) {
    int b = blockIdx.x, t = threadIdx.x;
    int id = ids[b * Xx + t];
    atomicOr(&g_bit[b * BW + (id >> 5)], 1u << (id & 31));
}
__global__ void k0e_kernel(const float* __restrict__ emb) {
    size_t base = ((size_t)blockIdx.x * 256 + threadIdx.x) * 16;
    int v = (int)(base / Dd);
    bool valid = v < VV;
    const float* src = emb + base;
    #pragma unroll
    for (int i = 0; i < 4; i++) {
        float4 f = valid ? *(const float4*)(src + i * 4) : make_float4(0.f, 0.f, 0.f, 0.f);
        float vs[4] = {f.x, f.y, f.z, f.w};
        #pragma unroll
        for (int u = 0; u < 4; u++) {
            __nv_bfloat16 hi = __float2bfloat16(vs[u]);
            __nv_bfloat16 lo = __float2bfloat16(vs[u] - __bfloat162float(hi));
            g_ebh[base + i * 4 + u] = hi;
            g_ebl[base + i * 4 + u] = lo;
        }
    }
}
__global__ void k0w_kernel(const float* __restrict__ w, int which) {
    size_t base = ((size_t)blockIdx.x * 256 + threadIdx.x) * 4;
    __nv_bfloat16* oh = which ? g_whh_h : g_wih_h;
    __nv_bfloat16* ol = which ? g_whh_l : g_wih_l;
    float4 f = *(const float4*)(w + base);
    float vs[4] = {f.x, f.y, f.z, f.w};
    #pragma unroll
    for (int u = 0; u < 4; u++) {
        __nv_bfloat16 hi = __float2bfloat16(vs[u]);
        __nv_bfloat16 lo = __float2bfloat16(vs[u] - __bfloat162float(hi));
        oh[base + u] = hi;
        ol[base + u] = lo;
    }
}
__global__ void k2x_kernel(const float* __restrict__ dec, int j) {
    int i = blockIdx.x * 256 + threadIdx.x;
    int b = i / Dd, d = i - b * Dd;
    float x = dec[((size_t)b * Jj + j) * Dd + d];
    __nv_bfloat16 hi = __float2bfloat16(x);
    g_xhb[i] = hi;
    g_xlb[i] = __float2bfloat16(x - __bfloat162float(hi));
}

// standalone k1h (prologue only)
__global__ void __launch_bounds__(256, 2) k1h_kernel(const float* __restrict__ bias,
                                                     int which) {
    extern __shared__ __align__(16) __nv_bfloat16 sm[];
    k1h_body(sm, blockIdx.x, blockIdx.y, bias, which);
}

// super1: [0,240)=k3, [240,312)=k1h-hh(next step), [312,568)=k2b
__global__ void __launch_bounds__(256, 2) super1_kernel(const float* __restrict__ enc,
                                                        const int* __restrict__ ids,
                                                        const float* __restrict__ b_hh,
                                                        int do_hh) {
    extern __shared__ __align__(16) __nv_bfloat16 sm[];
    int bx = blockIdx.x;
    if (bx < NB) {
        k3_body(sm, bx);
    } else if (bx < NB + 72) {
        if (do_hh) {
            int id = bx - NB;
            k1h_body(sm, id % 18, id / 18, b_hh, 1);
        }
    } else {
        int id = bx - (NB + 72);
        k2b_body((float*)sm, id >> 3, id & 7, enc, ids);
    }
}

// k2ah: GRU h-update (sums 4 K-quarters) + bf16 split
__global__ void k2ah_kernel() {
    int i = blockIdx.x * 256 + threadIdx.x;
    int d = i >> 5, b = i & 31;
    float gi0 = 0.f, gi1 = 0.f, gi2 = 0.f, gh0 = 0.f, gh1 = 0.f, gh2 = 0.f;
    #pragma unroll
    for (int z2 = 0; z2 < 4; z2++) {
        const float* gi = g_giT + z2 * GSZ;
        const float* gh = g_ghT + z2 * GSZ;
        gi0 += gi[i]; gi1 += gi[(Dd << 5) + i]; gi2 += gi[(2 * Dd << 5) + i];
        gh0 += gh[i]; gh1 += gh[(Dd << 5) + i]; gh2 += gh[(2 * Dd << 5) + i];
    }
    float r = sigf(gi0 + gh0);
    float z = sigf(gi1 + gh1);
    float n = tanhf(gi2 + r * gh2);
    int hi_ = b * Dd + d;
    float h = (1.f - z) * n + z * g_h[hi_];
    g_h[hi_] = h;
    __nv_bfloat16 hh = __float2bfloat16(h);
    g_hhb[hi_] = hh;
    g_hlb[hi_] = __float2bfloat16(h - __bfloat162float(hh));
}

// k2d: local softmax + context
__global__ void k2d_kernel(const float* __restrict__ enc) {
    __shared__ float sc[Xx];
    __shared__ float s_at[Xx];
    __shared__ float red[128];
    int b = blockIdx.y, t = threadIdx.x;
    int d0 = blockIdx.x * 128;
    sc[t] = g_attn[b * Xx + t];
    sc[t + 128] = g_attn[b * Xx + t + 128];
    __syncthreads();
    red[t] = fmaxf(sc[t], sc[t + 128]);
    __syncthreads();
    for (int s2 = 64; s2; s2 >>= 1) { if (t < s2) red[t] = fmaxf(red[t], red[t + s2]); __syncthreads(); }
    float m = red[0];
    __syncthreads();
    float e0 = expf(sc[t] - m), e1 = expf(sc[t + 128] - m);
    red[t] = e0 + e1;
    __syncthreads();
    for (int s2 = 64; s2; s2 >>= 1) { if (t < s2) red[t] += red[t + s2]; __syncthreads(); }
    float inv = 1.f / red[0];
    float a0_ = e0 * inv, a1_ = e1 * inv;
    s_at[t] = a0_;
    s_at[t + 128] = a1_;
    if (blockIdx.x == 0) {
        g_attn_n[b * Xx + t] = a0_;
        g_attn_n[b * Xx + t + 128] = a1_;
    }
    __syncthreads();
    const float* eb = enc + (size_t)b * Xx * Dd + d0 + t;
    float a0 = 0.f, a1 = 0.f, a2 = 0.f, a3 = 0.f;
    #pragma unroll 2
    for (int x = 0; x < Xx; x += 4) {
        a0 += s_at[x + 0] * eb[(size_t)(x + 0) * Dd];
        a1 += s_at[x + 1] * eb[(size_t)(x + 1) * Dd];
        a2 += s_at[x + 2] * eb[(size_t)(x + 2) * Dd];
        a3 += s_at[x + 3] * eb[(size_t)(x + 3) * Dd];
    }
    g_ctx[(size_t)b * Dd + d0 + t] = (a0 + a1) + (a2 + a3);
}

// k4: p_gen; reduce partials; scatter; argmax; x_next (+split)
__global__ void k4_kernel(const float* __restrict__ emb, const int* __restrict__ ids,
                          const float* __restrict__ dec,
                          const float* __restrict__ w_gen, const float* __restrict__ b_gen,
                          float* __restrict__ out, int j, int kstep, int k0) {
    __shared__ float rf[256];
    __shared__ unsigned long long rk[256];
    __shared__ float s_at[Xx];
    __shared__ int s_ids[Xx];
    __shared__ int s_am;
    __shared__ float s_pg;
    int b = blockIdx.x, t = threadIdx.x;

    const float* xr = k0 ? (dec + ((size_t)b * Jj + j) * Dd) : (g_x + (size_t)b * Dd);
    float pgp = 0.f;
    for (int d = t; d < Dd; d += 256)
        pgp += w_gen[d] * g_h[(size_t)b * Dd + d]
             + w_gen[Dd + d] * xr[d]
             + w_gen[2 * Dd + d] * g_ctx[(size_t)b * Dd + d];
    rf[t] = pgp; __syncthreads();
    for (int s2 = 128; s2; s2 >>= 1) { if (t < s2) rf[t] += rf[t + s2]; __syncthreads(); }
    if (t == 0) { s_pg = sigf(rf[0] + b_gen[0]); g_pgen[b] = s_pg; }
    __syncthreads();
    float pg = s_pg;
    __syncthreads();

    rf[t] = (t < NB) ? g_psum[b * NB + t] : 0.f;
    rk[t] = (t < NB) ? g_pkey[b * NB + t] : 0ull;
    s_ids[t] = ids[b * Xx + t];
    s_at[t] = g_attn_n[b * Xx + t];
    __syncthreads();
    for (int s2 = 128; s2; s2 >>= 1) {
        if (t < s2) {
            rf[t] += rf[t + s2];
            if (rk[t + s2] > rk[t]) rk[t] = rk[t + s2];
        }
        __syncthreads();
    }
    float inv = 1.f / rf[0];
    int vd = ~(unsigned)(rk[0] & 0xffffffffu);
    if (t == 0) g_inv[b] = inv;
    __syncthreads();

    const float* erow = g_e + (size_t)b * VP;
    float* orow = out + (((size_t)b * Jj + j) * Kk + kstep) * VV;
    float one_m = 1.f - pg;

    float dval = pg * erow[vd] * inv;
    unsigned long long best =
        ((unsigned long long)__float_as_uint(dval) << 32) | (unsigned)(~vd);
    {
        int v = s_ids[t];
        float a = 0.f;
        #pragma unroll 4
        for (int x2 = 0; x2 < Xx; x2++) a += (s_ids[x2] == v) ? s_at[x2] : 0.f;
        float full = pg * erow[v] * inv + one_m * a;
        orow[v] = full;
        unsigned long long key =
            ((unsigned long long)__float_as_uint(full) << 32) | (unsigned)(~v);
        if (key > best) best = key;
    }
    rk[t] = best; __syncthreads();
    for (int s2 = 128; s2; s2 >>= 1) {
        if (t < s2 && rk[t + s2] > rk[t]) rk[t] = rk[t + s2];
        __syncthreads();
    }
    if (t == 0) s_am = ~(unsigned)(rk[0] & 0xffffffffu);
    __syncthreads();
    int am = s_am;
    for (int d = t; d < Dd; d += 256) {
        float xv = emb[(size_t)am * Dd + d];
        int xi = b * Dd + d;
        g_x[xi] = xv;
        __nv_bfloat16 hi = __float2bfloat16(xv);
        g_xhb[xi] = hi;
        g_xlb[xi] = __float2bfloat16(xv - __bfloat162float(hi));
    }
}

// super2: [0,960)=k5w dense write, [960,1032)=k1h-ih(next step)
__global__ void __launch_bounds__(256, 2) super2_kernel(float* __restrict__ out,
                                                        const float* __restrict__ b_ih,
                                                        int j, int kstep, int do_ih) {
    extern __shared__ __align__(16) __nv_bfloat16 sm[];
    int bx = blockIdx.x;
    if (bx < 960) {
        int b = bx / 30, xc = bx % 30;
        int t = threadIdx.x;
        int v0 = xc * 1024 + t * 4;
        if (v0 >= VV) return;
        float sc = g_pgen[b] * g_inv[b];
        const float* erow = g_e + (size_t)b * VP;
        float* orow = out + (((size_t)b * Jj + j) * Kk + kstep) * VV;
        unsigned m = (g_bit[b * BW + (v0 >> 5)] >> (v0 & 31)) & 0xFu;
        if (v0 + 3 < VV) {
            float4 e4 = *(const float4*)(erow + v0);
            float o0 = sc * e4.x, o1 = sc * e4.y, o2 = sc * e4.z, o3 = sc * e4.w;
            if (m == 0u) {
                *(float2*)(orow + v0)     = make_float2(o0, o1);
                *(float2*)(orow + v0 + 2) = make_float2(o2, o3);
            } else {
                if (!(m & 1u)) orow[v0 + 0] = o0;
                if (!(m & 2u)) orow[v0 + 1] = o1;
                if (!(m & 4u)) orow[v0 + 2] = o2;
                if (!(m & 8u)) orow[v0 + 3] = o3;
            }
        } else {
            for (int v = v0; v < VV; v++)
                if (!((m >> (v - v0)) & 1u)) orow[v] = sc * erow[v];
        }
    } else if (do_ih) {
        int id = bx - 960;
        k1h_body(sm, id % 18, id / 18, b_ih, 0);
    }
}

extern "C" void kernel_launch(void* const* d_in, const int* in_sizes, int n_in,
                              void* d_out, int out_size) {
    const float* dec    = (const float*)d_in[0];
    const float* hidden = (const float*)d_in[1];
    const float* enc    = (const float*)d_in[2];
    const int*   ids    = (const int*)  d_in[3];
    int ei = (in_sizes[4] <= 16) ? 5 : 4;
    const float* emb   = (const float*)d_in[ei + 0];
    const float* w_ih  = (const float*)d_in[ei + 1];
    const float* w_hh  = (const float*)d_in[ei + 2];
    const float* b_ih  = (const float*)d_in[ei + 3];
    const float* b_hh  = (const float*)d_in[ei + 4];
    const float* w_gen = (const float*)d_in[ei + 5];
    const float* b_gen = (const float*)d_in[ei + 6];
    float* out = (float*)d_out;

    const int SMEM3 = SBUF * 2 * 2;  // 51200 bytes
    cudaFuncSetAttribute(k1h_kernel, cudaFuncAttributeMaxDynamicSharedMemorySize, SMEM3);
    cudaFuncSetAttribute(super1_kernel, cudaFuncAttributeMaxDynamicSharedMemorySize, SMEM3);
    cudaFuncSetAttribute(super2_kernel, cudaFuncAttributeMaxDynamicSharedMemorySize, SMEM3);

    // single stream, no events — super-kernels provide the overlap
    init_kernel<<<(Bz * Dd + 255) / 256, 256>>>(hidden);
    bit_kernel<<<Bz, Xx>>>(ids);
    k0e_kernel<<<(int)(((size_t)VP * Dd) / 4096), 256>>>(emb);
    k0w_kernel<<<1728, 256>>>(w_ih, 0);
    k0w_kernel<<<1728, 256>>>(w_hh, 1);
    k2x_kernel<<<96, 256>>>(dec, 0);
    k1h_kernel<<<dim3(18, 4), 256, SMEM3>>>(b_ih, 0);
    k1h_kernel<<<dim3(18, 4), 256, SMEM3>>>(b_hh, 1);

    for (int s = 0; s < Jj * Kk; s++) {
        int j = s >> 3, k = s & 7;
        int k0 = (k == 0);
        int more = (s + 1 < Jj * Kk);
        k2ah_kernel<<<96, 256>>>();
        super1_kernel<<<NB + 72 + 256, 256, SMEM3>>>(enc, ids, b_hh, more);
        k2d_kernel<<<dim3(6, Bz), 128>>>(enc);
        k4_kernel<<<Bz, 256>>>(emb, ids, dec, w_gen, b_gen, out, j, k, k0);
        if (more && ((s + 1) & 7) == 0) k2x_kernel<<<96, 256>>>(dec, (s + 1) >> 3);
        super2_kernel<<<960 + 72, 256, SMEM3>>>(out, b_ih, j, k, more);
    }
}